// round 14
// baseline (speedup 1.0000x reference)
#include <cuda_runtime.h>
#include <cuda_fp16.h>
#include <math.h>
#include <stdint.h>

#define BATCH 2
#define SEQ   2048
#define DMODEL 1024
#define NHEADS 16
#define HDIM  64
#define MROWS (BATCH*SEQ)          // 4096

// ---------------- scratch (device globals) ------------------------------------
__device__ __half g_h_h [(size_t)MROWS * DMODEL];          // LN out (fp16)
__device__ __half g_qkv_h[(size_t)MROWS * 3 * DMODEL];     // QKV (fp16)
__device__ __half g_y_h [(size_t)MROWS * DMODEL];          // attention out (fp16)
__device__ float  g_x2  [(size_t)MROWS * DMODEL];          // residual after attn (fp32)
__device__ __half g_a_h [(size_t)MROWS * 4 * DMODEL];      // MLP hidden (fp16)
__device__ float  g_part[(size_t)2 * MROWS * DMODEL];      // FC2 split-K partials (fp32)
__device__ __half g_wth_attn[(size_t)3 * DMODEL * DMODEL]; // [N,K] fp16
__device__ __half g_wth_proj[(size_t)DMODEL * DMODEL];
__device__ __half g_wth_fc  [(size_t)4 * DMODEL * DMODEL];
__device__ __half g_wth_fc2 [(size_t)4 * DMODEL * DMODEL];

// =========================== PTX helpers ======================================
__device__ __forceinline__ uint32_t pack_h2(float lo, float hi) {
    uint32_t u;
    asm("cvt.rn.f16x2.f32 %0, %1, %2;" : "=r"(u) : "f"(hi), "f"(lo));
    return u;
}
__device__ __forceinline__ void cp16(uint32_t dst, const void* src) {
    asm volatile("cp.async.cg.shared.global [%0], [%1], 16;" :: "r"(dst), "l"(src));
}
#define CP_COMMIT() asm volatile("cp.async.commit_group;" ::: "memory")
template <int N> __device__ __forceinline__ void cp_wait() {
    asm volatile("cp.async.wait_group %0;" :: "n"(N) : "memory");
}
#define LDSM4(r0, r1, r2, r3, addr) \
    asm volatile("ldmatrix.sync.aligned.m8n8.x4.shared.b16 {%0,%1,%2,%3}, [%4];" \
                 : "=r"(r0), "=r"(r1), "=r"(r2), "=r"(r3) : "r"(addr))
#define LDSM4T(r0, r1, r2, r3, addr) \
    asm volatile("ldmatrix.sync.aligned.m8n8.x4.trans.shared.b16 {%0,%1,%2,%3}, [%4];" \
                 : "=r"(r0), "=r"(r1), "=r"(r2), "=r"(r3) : "r"(addr))
#define MMA16816(d, a, b) \
    asm volatile("mma.sync.aligned.m16n8k16.row.col.f32.f16.f16.f32 " \
                 "{%0,%1,%2,%3}, {%4,%5,%6,%7}, {%8,%9}, {%0,%1,%2,%3};" \
                 : "+f"((d)[0]), "+f"((d)[1]), "+f"((d)[2]), "+f"((d)[3]) \
                 : "r"((a)[0]), "r"((a)[1]), "r"((a)[2]), "r"((a)[3]), \
                   "r"((b)[0]), "r"((b)[1]))

__device__ __forceinline__ float gelu_exact(float x) {
    return 0.5f * x * (1.0f + erff(x * 0.70710678118654752440f));
}

// ==================== LayerNorm: warp-per-row, 8 rows/block ====================
__global__ void __launch_bounds__(256)
layernorm_kernel(const float* __restrict__ src,
                 const float* __restrict__ w,
                 const float* __restrict__ b,
                 __half* __restrict__ dst) {
    const int lane = threadIdx.x & 31;
    const int row  = blockIdx.x * 8 + (threadIdx.x >> 5);
    const float4* srow = (const float4*)(src + (size_t)row * DMODEL);

    float4 v[8];
    float s = 0.f, q = 0.f;
    #pragma unroll
    for (int k = 0; k < 8; k++) {
        v[k] = srow[lane + 32 * k];
        s += v[k].x + v[k].y + v[k].z + v[k].w;
        q += v[k].x*v[k].x + v[k].y*v[k].y + v[k].z*v[k].z + v[k].w*v[k].w;
    }
    #pragma unroll
    for (int o = 16; o > 0; o >>= 1) {
        s += __shfl_xor_sync(0xffffffffu, s, o);
        q += __shfl_xor_sync(0xffffffffu, q, o);
    }
    const float mean = s * (1.0f / DMODEL);
    const float var  = q * (1.0f / DMODEL) - mean * mean;
    const float rstd = rsqrtf(var + 1e-5f);

    uint2* drow = (uint2*)(dst + (size_t)row * DMODEL);
    #pragma unroll
    for (int k = 0; k < 8; k++) {
        const float4 wv = ((const float4*)w)[lane + 32 * k];
        const float4 bv = ((const float4*)b)[lane + 32 * k];
        const float ox = (v[k].x - mean) * rstd * wv.x + bv.x;
        const float oy = (v[k].y - mean) * rstd * wv.y + bv.y;
        const float oz = (v[k].z - mean) * rstd * wv.z + bv.z;
        const float ow = (v[k].w - mean) * rstd * wv.w + bv.w;
        drow[lane + 32 * k] = make_uint2(pack_h2(ox, oy), pack_h2(oz, ow));
    }
}

// ============ fused weight transpose + fp16: all 4 weights, one launch ========
__global__ void transpose_all_kernel(const float* __restrict__ wa,
                                     const float* __restrict__ wp,
                                     const float* __restrict__ wf,
                                     const float* __restrict__ wf2,
                                     __half* __restrict__ oa,
                                     __half* __restrict__ op,
                                     __half* __restrict__ of,
                                     __half* __restrict__ of2) {
    __shared__ float t[32][33];
    const int bid = blockIdx.x;
    const float* src; __half* dst;
    int K, N, nb, kb;
    if (bid < 3072)      { const int b = bid;        src = wa;  dst = oa;  K = 1024; N = 3072; nb = (b % 96) * 32;  kb = (b / 96) * 32; }
    else if (bid < 4096) { const int b = bid - 3072; src = wp;  dst = op;  K = 1024; N = 1024; nb = (b % 32) * 32;  kb = (b / 32) * 32; }
    else if (bid < 8192) { const int b = bid - 4096; src = wf;  dst = of;  K = 1024; N = 4096; nb = (b % 128) * 32; kb = (b / 128) * 32; }
    else                 { const int b = bid - 8192; src = wf2; dst = of2; K = 4096; N = 1024; nb = (b % 32) * 32;  kb = (b / 32) * 32; }
    const int tx = threadIdx.x, ty = threadIdx.y;
    #pragma unroll
    for (int i = 0; i < 32; i += 8)
        t[ty + i][tx] = src[(size_t)(kb + ty + i) * N + nb + tx];
    __syncthreads();
    #pragma unroll
    for (int i = 0; i < 32; i += 8)
        dst[(size_t)(nb + ty + i) * K + kb + tx] = __float2half_rn(t[tx][ty + i]);
}

// ======================= fp16 tensor-core GEMM (mma.sync) =====================
// C[M,N] = A[M,K](fp16) @ Bt[N,K](fp16)^T (+ bias/epilogue), fp32 accum.
// 128x128 CTA tile, 8 warps (2x4), warp tile 64x32, BK=64, 3-stage cp.async.
// Split-K: gridDim.z CTAs each handle K contiguous columns (param K = per-split
// length; Kfull = row stride). EPI: 0 fp32+bias, 1 fp32+bias+res, 2 fp16 gelu,
// 3 fp16+bias, 4 raw fp32 partial (no bias) to Cout + z*MROWS*N.
template <int EPI>
__global__ void __launch_bounds__(256)
hgemm_kernel(const __half* __restrict__ A, const __half* __restrict__ Bt,
             const float* __restrict__ bias, const float* __restrict__ res,
             void* __restrict__ Cout, int N, int K, int Kfull) {
    extern __shared__ char smraw[];
    char* sm = smraw + ((1024 - ((uintptr_t)smraw & 1023)) & 1023);
    const uint32_t sbase = (uint32_t)__cvta_generic_to_shared(sm);

    const int tid  = threadIdx.x;
    const int lane = tid & 31, wid = tid >> 5;
    const int wm = wid >> 2, wn = wid & 3;
    const int bx = blockIdx.x, by = blockIdx.y;
    const int kz = blockIdx.z;
    const int NK = K >> 6;

    const int lrow = tid >> 1;
    const int lch0 = (tid & 1) * 4;

    float acc[4][4][4];
    #pragma unroll
    for (int mi = 0; mi < 4; mi++)
        #pragma unroll
        for (int ni = 0; ni < 4; ni++)
            #pragma unroll
            for (int e = 0; e < 4; e++) acc[mi][ni][e] = 0.f;

    const __half* Ag = A + (size_t)(by * 128 + lrow) * Kfull + (size_t)kz * K + lch0 * 8;
    const __half* Bg = Bt + (size_t)(bx * 128 + lrow) * Kfull + (size_t)kz * K + lch0 * 8;
    uint32_t swoff[4];
    #pragma unroll
    for (int c = 0; c < 4; c++) {
        const uint32_t off = (uint32_t)(lrow * 128 + (lch0 + c) * 16);
        swoff[c] = off ^ ((off >> 3) & 0x70);
    }

    #pragma unroll
    for (int c2 = 0; c2 < 2; c2++) {
        const uint32_t base = sbase + c2 * 32768;
        const int kh = c2 << 6;
        #pragma unroll
        for (int c = 0; c < 4; c++) {
            cp16(base + swoff[c], Ag + kh + c * 8);
            cp16(base + 16384 + swoff[c], Bg + kh + c * 8);
        }
        CP_COMMIT();
    }

    int stage = 0, nstage = 2;
    for (int kt = 0; kt < NK; kt++) {
        if (kt + 2 < NK) cp_wait<1>(); else cp_wait<0>();
        __syncthreads();

        if (kt + 2 < NK) {
            const uint32_t base = sbase + nstage * 32768;
            const int kh = (kt + 2) << 6;
            #pragma unroll
            for (int c = 0; c < 4; c++) {
                cp16(base + swoff[c], Ag + kh + c * 8);
                cp16(base + 16384 + swoff[c], Bg + kh + c * 8);
            }
            CP_COMMIT();
        }

        const uint32_t abase = sbase + stage * 32768;
        const uint32_t bbase = abase + 16384;
        #pragma unroll
        for (int ks = 0; ks < 4; ks++) {
            uint32_t af[4][4];
            #pragma unroll
            for (int mi = 0; mi < 4; mi++) {
                const int r = wm * 64 + mi * 16 + (lane & 7) + 8 * ((lane >> 3) & 1);
                const int cb = (ks * 16 + 8 * ((lane >> 4) & 1)) * 2;
                const uint32_t off = (uint32_t)(r * 128 + cb);
                LDSM4(af[mi][0], af[mi][1], af[mi][2], af[mi][3],
                      abase + (off ^ ((off >> 3) & 0x70)));
            }
            uint32_t bf[4][2];
            #pragma unroll
            for (int np = 0; np < 2; np++) {
                const int r = wn * 32 + np * 16 + (lane & 7) + 8 * ((lane >> 4) & 1);
                const int cb = (ks * 16 + 8 * ((lane >> 3) & 1)) * 2;
                const uint32_t off = (uint32_t)(r * 128 + cb);
                uint32_t b0, b1, b2, b3;
                LDSM4(b0, b1, b2, b3, bbase + (off ^ ((off >> 3) & 0x70)));
                bf[np * 2][0] = b0; bf[np * 2][1] = b1;
                bf[np * 2 + 1][0] = b2; bf[np * 2 + 1][1] = b3;
            }
            #pragma unroll
            for (int mi = 0; mi < 4; mi++)
                #pragma unroll
                for (int ni = 0; ni < 4; ni++)
                    MMA16816(acc[mi][ni], af[mi], bf[ni]);
        }

        stage = (stage == 2) ? 0 : stage + 1;
        nstage = (nstage == 2) ? 0 : nstage + 1;
    }

    const int row0 = by * 128 + wm * 64;
    const int col0 = bx * 128 + wn * 32;
    #pragma unroll
    for (int mi = 0; mi < 4; mi++) {
        #pragma unroll
        for (int ni = 0; ni < 4; ni++) {
            const int r = row0 + mi * 16 + (lane >> 2);
            const int c = col0 + ni * 8 + (lane & 3) * 2;
            if (EPI == 4) {
                float* C = (float*)Cout + (size_t)kz * MROWS * N;
                *(float2*)(C + (size_t)r * N + c) =
                    make_float2(acc[mi][ni][0], acc[mi][ni][1]);
                *(float2*)(C + (size_t)(r + 8) * N + c) =
                    make_float2(acc[mi][ni][2], acc[mi][ni][3]);
                continue;
            }
            const float b0 = bias[c], b1 = bias[c + 1];
            float v0 = acc[mi][ni][0] + b0, v1 = acc[mi][ni][1] + b1;
            float v2 = acc[mi][ni][2] + b0, v3 = acc[mi][ni][3] + b1;
            if (EPI == 1) {
                const float2 r0 = *(const float2*)(res + (size_t)r * N + c);
                const float2 r1 = *(const float2*)(res + (size_t)(r + 8) * N + c);
                v0 += r0.x; v1 += r0.y; v2 += r1.x; v3 += r1.y;
            }
            if (EPI == 2) {
                __half* C = (__half*)Cout;
                *(uint32_t*)(C + (size_t)r * N + c) =
                    pack_h2(gelu_exact(v0), gelu_exact(v1));
                *(uint32_t*)(C + (size_t)(r + 8) * N + c) =
                    pack_h2(gelu_exact(v2), gelu_exact(v3));
            } else if (EPI == 3) {
                __half* C = (__half*)Cout;
                *(uint32_t*)(C + (size_t)r * N + c) = pack_h2(v0, v1);
                *(uint32_t*)(C + (size_t)(r + 8) * N + c) = pack_h2(v2, v3);
            } else {
                float* C = (float*)Cout;
                *(float2*)(C + (size_t)r * N + c) = make_float2(v0, v1);
                *(float2*)(C + (size_t)(r + 8) * N + c) = make_float2(v2, v3);
            }
        }
    }
}

#define HGEMM_SMEM (3 * 32768 + 1024)

// ================= FC2 combine: out = x2 + bias + p0 + p1 =====================
__global__ void __launch_bounds__(256)
fc2_combine_kernel(const float* __restrict__ x2, const float* __restrict__ bias,
                   const float* __restrict__ part, float* __restrict__ out) {
    const size_t idx = (size_t)blockIdx.x * 256 + threadIdx.x;   // float4 index
    const float4 a  = ((const float4*)x2)[idx];
    const float4 p0 = ((const float4*)part)[idx];
    const float4 p1 = ((const float4*)part)[idx + (size_t)MROWS * DMODEL / 4];
    const float4 bv = ((const float4*)bias)[idx & (DMODEL / 4 - 1)];
    float4 o;
    o.x = a.x + bv.x + p0.x + p1.x;
    o.y = a.y + bv.y + p0.y + p1.y;
    o.z = a.z + bv.z + p0.z + p1.z;
    o.w = a.w + bv.w + p0.w + p1.w;
    ((float4*)out)[idx] = o;
}

// ================== Tensor-core flash attention (fp16 MMA) ====================
// grid (32 bh, 16 qtIdx) with qt = 15 - by  => heavy tiles scheduled FIRST.
// smem: Q 16KB @0 | 3 KV stages @16K+s*16K (K @+0, V @+8192). 64KB total.
#define ATT_SMEM_BYTES 65536
#define L2E_SCALED 0.1803368801111204f   // 0.125 * log2(e)

__global__ void __launch_bounds__(256)
attention_tc_kernel(const __half* __restrict__ qkv, __half* __restrict__ y) {
    extern __shared__ char smatt[];
    const uint32_t sbase = (uint32_t)__cvta_generic_to_shared(smatt);

    const int tid = threadIdx.x, lane = tid & 31, w = tid >> 5;
    const int bh = blockIdx.x;
    const int qt = 15 - blockIdx.y;
    const int b = bh >> 4, hh = bh & 15;
    const int q0 = qt * 128;
    const int nkt = 2 * qt + 2;

    const __half* qbase = qkv + (size_t)(b * SEQ + q0) * (3 * DMODEL) + hh * HDIM;
    const __half* kbg = qkv + (size_t)b * SEQ * (3 * DMODEL) + DMODEL + hh * HDIM;
    const __half* vbg = kbg + DMODEL;

    for (int i = tid; i < 1024; i += 256) {
        const int r = i >> 3, ch = i & 7;
        const uint32_t off = (uint32_t)(r * 128 + ch * 16);
        cp16(sbase + (off ^ ((off >> 3) & 0x70)), qbase + (size_t)r * (3 * DMODEL) + ch * 8);
    }
    for (int i = tid; i < 512; i += 256) {
        const int r = i >> 3, ch = i & 7;
        const uint32_t off = (uint32_t)(r * 128 + ch * 16);
        const uint32_t sw = off ^ ((off >> 3) & 0x70);
        cp16(sbase + 16384 + sw, kbg + (size_t)r * (3 * DMODEL) + ch * 8);
        cp16(sbase + 16384 + 8192 + sw, vbg + (size_t)r * (3 * DMODEL) + ch * 8);
    }
    CP_COMMIT();
    for (int i = tid; i < 512; i += 256) {
        const int r = i >> 3, ch = i & 7;
        const uint32_t off = (uint32_t)(r * 128 + ch * 16);
        const uint32_t sw = off ^ ((off >> 3) & 0x70);
        cp16(sbase + 32768 + sw, kbg + (size_t)(64 + r) * (3 * DMODEL) + ch * 8);
        cp16(sbase + 32768 + 8192 + sw, vbg + (size_t)(64 + r) * (3 * DMODEL) + ch * 8);
    }
    CP_COMMIT();

    float O[8][4];
    #pragma unroll
    for (int nj = 0; nj < 8; nj++)
        #pragma unroll
        for (int e = 0; e < 4; e++) O[nj][e] = 0.f;
    float zm0 = -INFINITY, zm1 = -INFINITY, l0 = 0.f, l1 = 0.f;
    uint32_t aQ[4][4];

    const int r0g = q0 + w * 16 + (lane >> 2);

    int stage = 0, nstage = 2;
    for (int kt = 0; kt < nkt; kt++) {
        __syncthreads();

        if (kt + 2 < nkt) {
            const uint32_t nb = sbase + 16384 + nstage * 16384;
            const int k0n = (kt + 2) * 64;
            for (int i = tid; i < 512; i += 256) {
                const int r = i >> 3, ch = i & 7;
                const uint32_t off = (uint32_t)(r * 128 + ch * 16);
                const uint32_t sw = off ^ ((off >> 3) & 0x70);
                cp16(nb + sw, kbg + (size_t)(k0n + r) * (3 * DMODEL) + ch * 8);
                cp16(nb + 8192 + sw, vbg + (size_t)(k0n + r) * (3 * DMODEL) + ch * 8);
            }
            CP_COMMIT();
            cp_wait<2>();
        } else if (kt + 1 < nkt) {
            cp_wait<1>();
        } else {
            cp_wait<0>();
        }

        const uint32_t kvb = sbase + 16384 + stage * 16384;

        if (kt == 0) {
            #pragma unroll
            for (int kc = 0; kc < 4; kc++) {
                const int g = lane >> 3;
                const int r = w * 16 + (g & 1) * 8 + (lane & 7);
                const int c = kc * 16 + (g >> 1) * 8;
                const uint32_t off = (uint32_t)(r * 128 + c * 2);
                LDSM4(aQ[kc][0], aQ[kc][1], aQ[kc][2], aQ[kc][3],
                      sbase + (off ^ ((off >> 3) & 0x70)));
            }
        }

        const int k0 = kt * 64;

        float Sf[8][4];
        #pragma unroll
        for (int nj = 0; nj < 8; nj++)
            #pragma unroll
            for (int e = 0; e < 4; e++) Sf[nj][e] = 0.f;
        #pragma unroll
        for (int kc = 0; kc < 4; kc++) {
            #pragma unroll
            for (int j2 = 0; j2 < 4; j2++) {
                const int g = lane >> 3;
                const int r = j2 * 16 + (g >> 1) * 8 + (lane & 7);
                const int c = kc * 16 + (g & 1) * 8;
                const uint32_t off = (uint32_t)(r * 128 + c * 2);
                uint32_t b0, b1, b2, b3;
                LDSM4(b0, b1, b2, b3, kvb + (off ^ ((off >> 3) & 0x70)));
                uint32_t bA[2] = {b0, b1}, bB[2] = {b2, b3};
                MMA16816(Sf[2 * j2], aQ[kc], bA);
                MMA16816(Sf[2 * j2 + 1], aQ[kc], bB);
            }
        }

        const bool domask = (k0 + 63 > q0);
        float m0 = zm0, m1 = zm1;
        #pragma unroll
        for (int nj = 0; nj < 8; nj++) {
            const int cg = k0 + nj * 8 + (lane & 3) * 2;
            #pragma unroll
            for (int e = 0; e < 2; e++) {
                float z0 = Sf[nj][e] * L2E_SCALED;
                float z1 = Sf[nj][2 + e] * L2E_SCALED;
                if (domask) {
                    if (cg + e > r0g)     z0 = -INFINITY;
                    if (cg + e > r0g + 8) z1 = -INFINITY;
                }
                Sf[nj][e] = z0; Sf[nj][2 + e] = z1;
                m0 = fmaxf(m0, z0); m1 = fmaxf(m1, z1);
            }
        }
        m0 = fmaxf(m0, __shfl_xor_sync(0xffffffffu, m0, 1));
        m0 = fmaxf(m0, __shfl_xor_sync(0xffffffffu, m0, 2));
        m1 = fmaxf(m1, __shfl_xor_sync(0xffffffffu, m1, 1));
        m1 = fmaxf(m1, __shfl_xor_sync(0xffffffffu, m1, 2));
        const float c0 = exp2f(zm0 - m0);
        const float c1 = exp2f(zm1 - m1);
        zm0 = m0; zm1 = m1;
        l0 *= c0; l1 *= c1;
        #pragma unroll
        for (int nj = 0; nj < 8; nj++) {
            O[nj][0] *= c0; O[nj][1] *= c0;
            O[nj][2] *= c1; O[nj][3] *= c1;
        }

        __half2 p01[8], p23[8];
        #pragma unroll
        for (int nj = 0; nj < 8; nj++) {
            p01[nj] = h2exp2(__floats2half2_rn(Sf[nj][0] - m0, Sf[nj][1] - m0));
            p23[nj] = h2exp2(__floats2half2_rn(Sf[nj][2] - m1, Sf[nj][3] - m1));
            const float2 f01 = __half22float2(p01[nj]);
            const float2 f23 = __half22float2(p23[nj]);
            l0 += f01.x + f01.y;
            l1 += f23.x + f23.y;
        }

        #pragma unroll
        for (int kc = 0; kc < 4; kc++) {
            uint32_t aP[4];
            aP[0] = *(uint32_t*)&p01[2 * kc];
            aP[1] = *(uint32_t*)&p23[2 * kc];
            aP[2] = *(uint32_t*)&p01[2 * kc + 1];
            aP[3] = *(uint32_t*)&p23[2 * kc + 1];
            #pragma unroll
            for (int j2 = 0; j2 < 4; j2++) {
                const int g = lane >> 3;
                const int r = kc * 16 + (g & 1) * 8 + (lane & 7);
                const int c = j2 * 16 + (g >> 1) * 8;
                const uint32_t off = (uint32_t)(r * 128 + c * 2);
                uint32_t b0, b1, b2, b3;
                LDSM4T(b0, b1, b2, b3, kvb + 8192 + (off ^ ((off >> 3) & 0x70)));
                uint32_t bA[2] = {b0, b1}, bB[2] = {b2, b3};
                MMA16816(O[2 * j2], aP, bA);
                MMA16816(O[2 * j2 + 1], aP, bB);
            }
        }

        stage = (stage == 2) ? 0 : stage + 1;
        nstage = (nstage == 2) ? 0 : nstage + 1;
    }

    l0 += __shfl_xor_sync(0xffffffffu, l0, 1);
    l0 += __shfl_xor_sync(0xffffffffu, l0, 2);
    l1 += __shfl_xor_sync(0xffffffffu, l1, 1);
    l1 += __shfl_xor_sync(0xffffffffu, l1, 2);
    const float i0 = 1.0f / l0, i1 = 1.0f / l1;

    __half* y0 = y + (size_t)(b * SEQ + r0g) * DMODEL + hh * HDIM;
    __half* y1 = y0 + (size_t)8 * DMODEL;
    #pragma unroll
    for (int nj = 0; nj < 8; nj++) {
        const int col = nj * 8 + (lane & 3) * 2;
        *(uint32_t*)(y0 + col) = pack_h2(O[nj][0] * i0, O[nj][1] * i0);
        *(uint32_t*)(y1 + col) = pack_h2(O[nj][2] * i1, O[nj][3] * i1);
    }
}

// =============================== launcher =====================================
extern "C" void kernel_launch(void* const* d_in, const int* in_sizes, int n_in,
                              void* d_out, int out_size) {
    const float* x      = (const float*)d_in[0];
    const float* ln1_w  = (const float*)d_in[1];
    const float* ln1_b  = (const float*)d_in[2];
    const float* ln2_w  = (const float*)d_in[3];
    const float* ln2_b  = (const float*)d_in[4];
    const float* w_attn = (const float*)d_in[5];
    const float* b_attn = (const float*)d_in[6];
    const float* w_proj = (const float*)d_in[7];
    const float* b_proj = (const float*)d_in[8];
    const float* w_fc   = (const float*)d_in[9];
    const float* b_fc   = (const float*)d_in[10];
    const float* w_fc2  = (const float*)d_in[11];
    const float* b_fc2  = (const float*)d_in[12];
    float* out = (float*)d_out;

    __half *h_h, *qkv_h, *y_h, *a_h, *wth_attn, *wth_proj, *wth_fc, *wth_fc2;
    float *x2, *part;
    cudaGetSymbolAddress((void**)&h_h,      g_h_h);
    cudaGetSymbolAddress((void**)&qkv_h,    g_qkv_h);
    cudaGetSymbolAddress((void**)&y_h,      g_y_h);
    cudaGetSymbolAddress((void**)&x2,       g_x2);
    cudaGetSymbolAddress((void**)&a_h,      g_a_h);
    cudaGetSymbolAddress((void**)&part,     g_part);
    cudaGetSymbolAddress((void**)&wth_attn, g_wth_attn);
    cudaGetSymbolAddress((void**)&wth_proj, g_wth_proj);
    cudaGetSymbolAddress((void**)&wth_fc,   g_wth_fc);
    cudaGetSymbolAddress((void**)&wth_fc2,  g_wth_fc2);

    cudaFuncSetAttribute(attention_tc_kernel,
                         cudaFuncAttributeMaxDynamicSharedMemorySize, ATT_SMEM_BYTES);
    cudaFuncSetAttribute(hgemm_kernel<1>,
                         cudaFuncAttributeMaxDynamicSharedMemorySize, HGEMM_SMEM);
    cudaFuncSetAttribute(hgemm_kernel<2>,
                         cudaFuncAttributeMaxDynamicSharedMemorySize, HGEMM_SMEM);
    cudaFuncSetAttribute(hgemm_kernel<3>,
                         cudaFuncAttributeMaxDynamicSharedMemorySize, HGEMM_SMEM);
    cudaFuncSetAttribute(hgemm_kernel<4>,
                         cudaFuncAttributeMaxDynamicSharedMemorySize, HGEMM_SMEM);

    // Side stream + events, lazily created on the FIRST (uncaptured) call.
    static cudaStream_t s2 = nullptr;
    static cudaEvent_t evFork = nullptr, evJoin = nullptr;
    if (s2 == nullptr) {
        cudaStreamCreateWithFlags(&s2, cudaStreamNonBlocking);
        cudaEventCreateWithFlags(&evFork, cudaEventDisableTiming);
        cudaEventCreateWithFlags(&evJoin, cudaEventDisableTiming);
    }

    // 0) fork: weight transpose on s2, LN1 on main stream
    cudaEventRecord(evFork, 0);
    cudaStreamWaitEvent(s2, evFork, 0);
    {
        dim3 tb(32, 8);
        transpose_all_kernel<<<12288, tb, 0, s2>>>(w_attn, w_proj, w_fc, w_fc2,
                                                   wth_attn, wth_proj, wth_fc, wth_fc2);
    }
    cudaEventRecord(evJoin, s2);

    // 1) h = LN1(x)  (fp16)
    layernorm_kernel<<<MROWS / 8, 256>>>(x, ln1_w, ln1_b, h_h);

    cudaStreamWaitEvent(0, evJoin, 0);

    // 2) qkv = h @ w_attn + b_attn       [4096,3072] K=1024  (fp16 out)
    hgemm_kernel<3><<<dim3(3 * DMODEL / 128, MROWS / 128), 256, HGEMM_SMEM>>>(
        h_h, wth_attn, b_attn, nullptr, qkv_h, 3 * DMODEL, DMODEL, DMODEL);

    // 3) y = attention(qkv)  (heavy-first, fp16 out)
    {
        dim3 grid(BATCH * NHEADS, SEQ / 128);
        attention_tc_kernel<<<grid, 256, ATT_SMEM_BYTES>>>(qkv_h, y_h);
    }

    // 4) x2 = x + y @ w_proj + b_proj    [4096,1024] K=1024  (fp32 out)
    hgemm_kernel<1><<<dim3(DMODEL / 128, MROWS / 128), 256, HGEMM_SMEM>>>(
        y_h, wth_proj, b_proj, x, x2, DMODEL, DMODEL, DMODEL);

    // 5) h = LN2(x2)  (fp16)
    layernorm_kernel<<<MROWS / 8, 256>>>(x2, ln2_w, ln2_b, h_h);

    // 6) a = gelu(h @ w_fc + b_fc)       [4096,4096] K=1024  (fp16 out)
    hgemm_kernel<2><<<dim3(4 * DMODEL / 128, MROWS / 128), 256, HGEMM_SMEM>>>(
        h_h, wth_fc, b_fc, nullptr, a_h, 4 * DMODEL, DMODEL, DMODEL);

    // 7) FC2 split-K=2: partials = a @ w_fc2 (each z: K=2048)   [4096,1024]
    hgemm_kernel<4><<<dim3(DMODEL / 128, MROWS / 128, 2), 256, HGEMM_SMEM>>>(
        a_h, wth_fc2, nullptr, nullptr, part, DMODEL, 2 * DMODEL, 4 * DMODEL);

    // 8) out = x2 + b_fc2 + p0 + p1
    fc2_combine_kernel<<<MROWS * DMODEL / 4 / 256, 256>>>(x2, b_fc2, part, out);
}

// round 15
// speedup vs baseline: 1.0159x; 1.0159x over previous
#include <cuda_runtime.h>
#include <cuda_fp16.h>
#include <math.h>
#include <stdint.h>

#define BATCH 2
#define SEQ   2048
#define DMODEL 1024
#define NHEADS 16
#define HDIM  64
#define MROWS (BATCH*SEQ)          // 4096

#define L2E_SCALED 0.1803368801111204f   // 0.125 * log2(e), folded into Q at QKV epilogue

// ---------------- scratch (device globals) ------------------------------------
__device__ __half g_h_h [(size_t)MROWS * DMODEL];          // LN out (fp16)
__device__ __half g_qkv_h[(size_t)MROWS * 3 * DMODEL];     // QKV (fp16, Q pre-scaled)
__device__ __half g_y_h [(size_t)MROWS * DMODEL];          // attention out (fp16)
__device__ float  g_x2  [(size_t)MROWS * DMODEL];          // residual after attn (fp32)
__device__ __half g_a_h [(size_t)MROWS * 4 * DMODEL];      // MLP hidden (fp16)
__device__ __half g_wth_attn[(size_t)3 * DMODEL * DMODEL]; // [N,K] fp16
__device__ __half g_wth_proj[(size_t)DMODEL * DMODEL];
__device__ __half g_wth_fc  [(size_t)4 * DMODEL * DMODEL];
__device__ __half g_wth_fc2 [(size_t)4 * DMODEL * DMODEL];

// =========================== PTX helpers ======================================
__device__ __forceinline__ uint32_t pack_h2(float lo, float hi) {
    uint32_t u;
    asm("cvt.rn.f16x2.f32 %0, %1, %2;" : "=r"(u) : "f"(hi), "f"(lo));
    return u;
}
__device__ __forceinline__ void cp16(uint32_t dst, const void* src) {
    asm volatile("cp.async.cg.shared.global [%0], [%1], 16;" :: "r"(dst), "l"(src));
}
#define CP_COMMIT() asm volatile("cp.async.commit_group;" ::: "memory")
template <int N> __device__ __forceinline__ void cp_wait() {
    asm volatile("cp.async.wait_group %0;" :: "n"(N) : "memory");
}
#define LDSM4(r0, r1, r2, r3, addr) \
    asm volatile("ldmatrix.sync.aligned.m8n8.x4.shared.b16 {%0,%1,%2,%3}, [%4];" \
                 : "=r"(r0), "=r"(r1), "=r"(r2), "=r"(r3) : "r"(addr))
#define LDSM4T(r0, r1, r2, r3, addr) \
    asm volatile("ldmatrix.sync.aligned.m8n8.x4.trans.shared.b16 {%0,%1,%2,%3}, [%4];" \
                 : "=r"(r0), "=r"(r1), "=r"(r2), "=r"(r3) : "r"(addr))
#define MMA16816(d, a, b) \
    asm volatile("mma.sync.aligned.m16n8k16.row.col.f32.f16.f16.f32 " \
                 "{%0,%1,%2,%3}, {%4,%5,%6,%7}, {%8,%9}, {%0,%1,%2,%3};" \
                 : "+f"((d)[0]), "+f"((d)[1]), "+f"((d)[2]), "+f"((d)[3]) \
                 : "r"((a)[0]), "r"((a)[1]), "r"((a)[2]), "r"((a)[3]), \
                   "r"((b)[0]), "r"((b)[1]))

__device__ __forceinline__ float gelu_exact(float x) {
    return 0.5f * x * (1.0f + erff(x * 0.70710678118654752440f));
}

// ==================== LayerNorm: warp-per-row, 8 rows/block ====================
__global__ void __launch_bounds__(256)
layernorm_kernel(const float* __restrict__ src,
                 const float* __restrict__ w,
                 const float* __restrict__ b,
                 __half* __restrict__ dst) {
    const int lane = threadIdx.x & 31;
    const int row  = blockIdx.x * 8 + (threadIdx.x >> 5);
    const float4* srow = (const float4*)(src + (size_t)row * DMODEL);

    float4 v[8];
    float s = 0.f, q = 0.f;
    #pragma unroll
    for (int k = 0; k < 8; k++) {
        v[k] = srow[lane + 32 * k];
        s += v[k].x + v[k].y + v[k].z + v[k].w;
        q += v[k].x*v[k].x + v[k].y*v[k].y + v[k].z*v[k].z + v[k].w*v[k].w;
    }
    #pragma unroll
    for (int o = 16; o > 0; o >>= 1) {
        s += __shfl_xor_sync(0xffffffffu, s, o);
        q += __shfl_xor_sync(0xffffffffu, q, o);
    }
    const float mean = s * (1.0f / DMODEL);
    const float var  = q * (1.0f / DMODEL) - mean * mean;
    const float rstd = rsqrtf(var + 1e-5f);

    uint2* drow = (uint2*)(dst + (size_t)row * DMODEL);
    #pragma unroll
    for (int k = 0; k < 8; k++) {
        const float4 wv = ((const float4*)w)[lane + 32 * k];
        const float4 bv = ((const float4*)b)[lane + 32 * k];
        const float ox = (v[k].x - mean) * rstd * wv.x + bv.x;
        const float oy = (v[k].y - mean) * rstd * wv.y + bv.y;
        const float oz = (v[k].z - mean) * rstd * wv.z + bv.z;
        const float ow = (v[k].w - mean) * rstd * wv.w + bv.w;
        drow[lane + 32 * k] = make_uint2(pack_h2(ox, oy), pack_h2(oz, ow));
    }
}

// ============ fused weight transpose + fp16: all 4 weights, one launch ========
__global__ void transpose_all_kernel(const float* __restrict__ wa,
                                     const float* __restrict__ wp,
                                     const float* __restrict__ wf,
                                     const float* __restrict__ wf2,
                                     __half* __restrict__ oa,
                                     __half* __restrict__ op,
                                     __half* __restrict__ of,
                                     __half* __restrict__ of2) {
    __shared__ float t[32][33];
    const int bid = blockIdx.x;
    const float* src; __half* dst;
    int K, N, nb, kb;
    if (bid < 3072)      { const int b = bid;        src = wa;  dst = oa;  K = 1024; N = 3072; nb = (b % 96) * 32;  kb = (b / 96) * 32; }
    else if (bid < 4096) { const int b = bid - 3072; src = wp;  dst = op;  K = 1024; N = 1024; nb = (b % 32) * 32;  kb = (b / 32) * 32; }
    else if (bid < 8192) { const int b = bid - 4096; src = wf;  dst = of;  K = 1024; N = 4096; nb = (b % 128) * 32; kb = (b / 128) * 32; }
    else                 { const int b = bid - 8192; src = wf2; dst = of2; K = 4096; N = 1024; nb = (b % 32) * 32;  kb = (b / 32) * 32; }
    const int tx = threadIdx.x, ty = threadIdx.y;
    #pragma unroll
    for (int i = 0; i < 32; i += 8)
        t[ty + i][tx] = src[(size_t)(kb + ty + i) * N + nb + tx];
    __syncthreads();
    #pragma unroll
    for (int i = 0; i < 32; i += 8)
        dst[(size_t)(nb + ty + i) * K + kb + tx] = __float2half_rn(t[tx][ty + i]);
}

// ======================= fp16 tensor-core GEMM (mma.sync) =====================
// C[M,N] = A[M,K](fp16) @ Bt[N,K](fp16)^T + bias (+ epilogue), fp32 accum.
// 128x128 CTA tile, 8 warps (2x4), warp tile 64x32, BK=64, 3-stage cp.async.
// EPI: 0 fp32+bias, 1 fp32+bias+res, 2 fp16 gelu, 3 fp16+bias with Q columns
// (c < DMODEL) pre-scaled by L2E_SCALED for the attention softmax.
template <int EPI>
__global__ void __launch_bounds__(256)
hgemm_kernel(const __half* __restrict__ A, const __half* __restrict__ Bt,
             const float* __restrict__ bias, const float* __restrict__ res,
             void* __restrict__ Cout, int N, int K) {
    extern __shared__ char smraw[];
    char* sm = smraw + ((1024 - ((uintptr_t)smraw & 1023)) & 1023);
    const uint32_t sbase = (uint32_t)__cvta_generic_to_shared(sm);

    const int tid  = threadIdx.x;
    const int lane = tid & 31, wid = tid >> 5;
    const int wm = wid >> 2, wn = wid & 3;
    const int bx = blockIdx.x, by = blockIdx.y;
    const int NK = K >> 6;

    const int lrow = tid >> 1;
    const int lch0 = (tid & 1) * 4;

    float acc[4][4][4];
    #pragma unroll
    for (int mi = 0; mi < 4; mi++)
        #pragma unroll
        for (int ni = 0; ni < 4; ni++)
            #pragma unroll
            for (int e = 0; e < 4; e++) acc[mi][ni][e] = 0.f;

    const __half* Ag = A + (size_t)(by * 128 + lrow) * K + lch0 * 8;
    const __half* Bg = Bt + (size_t)(bx * 128 + lrow) * K + lch0 * 8;
    uint32_t swoff[4];
    #pragma unroll
    for (int c = 0; c < 4; c++) {
        const uint32_t off = (uint32_t)(lrow * 128 + (lch0 + c) * 16);
        swoff[c] = off ^ ((off >> 3) & 0x70);
    }

    #pragma unroll
    for (int c2 = 0; c2 < 2; c2++) {
        const uint32_t base = sbase + c2 * 32768;
        const int kh = c2 << 6;
        #pragma unroll
        for (int c = 0; c < 4; c++) {
            cp16(base + swoff[c], Ag + kh + c * 8);
            cp16(base + 16384 + swoff[c], Bg + kh + c * 8);
        }
        CP_COMMIT();
    }

    int stage = 0, nstage = 2;
    for (int kt = 0; kt < NK; kt++) {
        if (kt + 2 < NK) cp_wait<1>(); else cp_wait<0>();
        __syncthreads();

        if (kt + 2 < NK) {
            const uint32_t base = sbase + nstage * 32768;
            const int kh = (kt + 2) << 6;
            #pragma unroll
            for (int c = 0; c < 4; c++) {
                cp16(base + swoff[c], Ag + kh + c * 8);
                cp16(base + 16384 + swoff[c], Bg + kh + c * 8);
            }
            CP_COMMIT();
        }

        const uint32_t abase = sbase + stage * 32768;
        const uint32_t bbase = abase + 16384;
        #pragma unroll
        for (int ks = 0; ks < 4; ks++) {
            uint32_t af[4][4];
            #pragma unroll
            for (int mi = 0; mi < 4; mi++) {
                const int r = wm * 64 + mi * 16 + (lane & 7) + 8 * ((lane >> 3) & 1);
                const int cb = (ks * 16 + 8 * ((lane >> 4) & 1)) * 2;
                const uint32_t off = (uint32_t)(r * 128 + cb);
                LDSM4(af[mi][0], af[mi][1], af[mi][2], af[mi][3],
                      abase + (off ^ ((off >> 3) & 0x70)));
            }
            uint32_t bf[4][2];
            #pragma unroll
            for (int np = 0; np < 2; np++) {
                const int r = wn * 32 + np * 16 + (lane & 7) + 8 * ((lane >> 4) & 1);
                const int cb = (ks * 16 + 8 * ((lane >> 3) & 1)) * 2;
                const uint32_t off = (uint32_t)(r * 128 + cb);
                uint32_t b0, b1, b2, b3;
                LDSM4(b0, b1, b2, b3, bbase + (off ^ ((off >> 3) & 0x70)));
                bf[np * 2][0] = b0; bf[np * 2][1] = b1;
                bf[np * 2 + 1][0] = b2; bf[np * 2 + 1][1] = b3;
            }
            #pragma unroll
            for (int mi = 0; mi < 4; mi++)
                #pragma unroll
                for (int ni = 0; ni < 4; ni++)
                    MMA16816(acc[mi][ni], af[mi], bf[ni]);
        }

        stage = (stage == 2) ? 0 : stage + 1;
        nstage = (nstage == 2) ? 0 : nstage + 1;
    }

    const int row0 = by * 128 + wm * 64;
    const int col0 = bx * 128 + wn * 32;
    #pragma unroll
    for (int mi = 0; mi < 4; mi++) {
        #pragma unroll
        for (int ni = 0; ni < 4; ni++) {
            const int r = row0 + mi * 16 + (lane >> 2);
            const int c = col0 + ni * 8 + (lane & 3) * 2;
            const float b0 = bias[c], b1 = bias[c + 1];
            float v0 = acc[mi][ni][0] + b0, v1 = acc[mi][ni][1] + b1;
            float v2 = acc[mi][ni][2] + b0, v3 = acc[mi][ni][3] + b1;
            if (EPI == 1) {
                const float2 r0 = *(const float2*)(res + (size_t)r * N + c);
                const float2 r1 = *(const float2*)(res + (size_t)(r + 8) * N + c);
                v0 += r0.x; v1 += r0.y; v2 += r1.x; v3 += r1.y;
            }
            if (EPI == 2) {
                __half* C = (__half*)Cout;
                *(uint32_t*)(C + (size_t)r * N + c) =
                    pack_h2(gelu_exact(v0), gelu_exact(v1));
                *(uint32_t*)(C + (size_t)(r + 8) * N + c) =
                    pack_h2(gelu_exact(v2), gelu_exact(v3));
            } else if (EPI == 3) {
                // pre-scale Q columns (c < DMODEL) for base-2 softmax
                const float qs = (c < DMODEL) ? L2E_SCALED : 1.0f;
                __half* C = (__half*)Cout;
                *(uint32_t*)(C + (size_t)r * N + c) = pack_h2(v0 * qs, v1 * qs);
                *(uint32_t*)(C + (size_t)(r + 8) * N + c) = pack_h2(v2 * qs, v3 * qs);
            } else {
                float* C = (float*)Cout;
                *(float2*)(C + (size_t)r * N + c) = make_float2(v0, v1);
                *(float2*)(C + (size_t)(r + 8) * N + c) = make_float2(v2, v3);
            }
        }
    }
}

#define HGEMM_SMEM (3 * 32768 + 1024)

// ================== Tensor-core flash attention (fp16 MMA) ====================
// grid (32 bh, 16 qtIdx) with qt = 15 - by  => heavy tiles scheduled FIRST.
// Q pre-scaled by L2E_SCALED at the QKV epilogue: S from MMA is already log2-domain.
// smem: Q 16KB @0 | 3 KV stages @16K+s*16K (K @+0, V @+8192). 64KB total.
#define ATT_SMEM_BYTES 65536

__global__ void __launch_bounds__(256)
attention_tc_kernel(const __half* __restrict__ qkv, __half* __restrict__ y) {
    extern __shared__ char smatt[];
    const uint32_t sbase = (uint32_t)__cvta_generic_to_shared(smatt);

    const int tid = threadIdx.x, lane = tid & 31, w = tid >> 5;
    const int bh = blockIdx.x;
    const int qt = 15 - blockIdx.y;
    const int b = bh >> 4, hh = bh & 15;
    const int q0 = qt * 128;
    const int nkt = 2 * qt + 2;

    const __half* qbase = qkv + (size_t)(b * SEQ + q0) * (3 * DMODEL) + hh * HDIM;
    const __half* kbg = qkv + (size_t)b * SEQ * (3 * DMODEL) + DMODEL + hh * HDIM;
    const __half* vbg = kbg + DMODEL;

    for (int i = tid; i < 1024; i += 256) {
        const int r = i >> 3, ch = i & 7;
        const uint32_t off = (uint32_t)(r * 128 + ch * 16);
        cp16(sbase + (off ^ ((off >> 3) & 0x70)), qbase + (size_t)r * (3 * DMODEL) + ch * 8);
    }
    for (int i = tid; i < 512; i += 256) {
        const int r = i >> 3, ch = i & 7;
        const uint32_t off = (uint32_t)(r * 128 + ch * 16);
        const uint32_t sw = off ^ ((off >> 3) & 0x70);
        cp16(sbase + 16384 + sw, kbg + (size_t)r * (3 * DMODEL) + ch * 8);
        cp16(sbase + 16384 + 8192 + sw, vbg + (size_t)r * (3 * DMODEL) + ch * 8);
    }
    CP_COMMIT();
    for (int i = tid; i < 512; i += 256) {
        const int r = i >> 3, ch = i & 7;
        const uint32_t off = (uint32_t)(r * 128 + ch * 16);
        const uint32_t sw = off ^ ((off >> 3) & 0x70);
        cp16(sbase + 32768 + sw, kbg + (size_t)(64 + r) * (3 * DMODEL) + ch * 8);
        cp16(sbase + 32768 + 8192 + sw, vbg + (size_t)(64 + r) * (3 * DMODEL) + ch * 8);
    }
    CP_COMMIT();

    float O[8][4];
    #pragma unroll
    for (int nj = 0; nj < 8; nj++)
        #pragma unroll
        for (int e = 0; e < 4; e++) O[nj][e] = 0.f;
    float zm0 = -INFINITY, zm1 = -INFINITY, l0 = 0.f, l1 = 0.f;
    uint32_t aQ[4][4];

    const int r0g = q0 + w * 16 + (lane >> 2);

    int stage = 0, nstage = 2;
    for (int kt = 0; kt < nkt; kt++) {
        __syncthreads();

        if (kt + 2 < nkt) {
            const uint32_t nb = sbase + 16384 + nstage * 16384;
            const int k0n = (kt + 2) * 64;
            for (int i = tid; i < 512; i += 256) {
                const int r = i >> 3, ch = i & 7;
                const uint32_t off = (uint32_t)(r * 128 + ch * 16);
                const uint32_t sw = off ^ ((off >> 3) & 0x70);
                cp16(nb + sw, kbg + (size_t)(k0n + r) * (3 * DMODEL) + ch * 8);
                cp16(nb + 8192 + sw, vbg + (size_t)(k0n + r) * (3 * DMODEL) + ch * 8);
            }
            CP_COMMIT();
            cp_wait<2>();
        } else if (kt + 1 < nkt) {
            cp_wait<1>();
        } else {
            cp_wait<0>();
        }

        const uint32_t kvb = sbase + 16384 + stage * 16384;

        if (kt == 0) {
            #pragma unroll
            for (int kc = 0; kc < 4; kc++) {
                const int g = lane >> 3;
                const int r = w * 16 + (g & 1) * 8 + (lane & 7);
                const int c = kc * 16 + (g >> 1) * 8;
                const uint32_t off = (uint32_t)(r * 128 + c * 2);
                LDSM4(aQ[kc][0], aQ[kc][1], aQ[kc][2], aQ[kc][3],
                      sbase + (off ^ ((off >> 3) & 0x70)));
            }
        }

        const int k0 = kt * 64;

        // ---- S = Q K^T  (log2 domain: Q pre-scaled) ----
        float Sf[8][4];
        #pragma unroll
        for (int nj = 0; nj < 8; nj++)
            #pragma unroll
            for (int e = 0; e < 4; e++) Sf[nj][e] = 0.f;
        #pragma unroll
        for (int kc = 0; kc < 4; kc++) {
            #pragma unroll
            for (int j2 = 0; j2 < 4; j2++) {
                const int g = lane >> 3;
                const int r = j2 * 16 + (g >> 1) * 8 + (lane & 7);
                const int c = kc * 16 + (g & 1) * 8;
                const uint32_t off = (uint32_t)(r * 128 + c * 2);
                uint32_t b0, b1, b2, b3;
                LDSM4(b0, b1, b2, b3, kvb + (off ^ ((off >> 3) & 0x70)));
                uint32_t bA[2] = {b0, b1}, bB[2] = {b2, b3};
                MMA16816(Sf[2 * j2], aQ[kc], bA);
                MMA16816(Sf[2 * j2 + 1], aQ[kc], bB);
            }
        }

        // ---- online softmax scan (mask-specialized) ----
        float m0 = zm0, m1 = zm1;
        if (k0 + 63 > q0) {
            // masked iterations (last two per tile)
            #pragma unroll
            for (int nj = 0; nj < 8; nj++) {
                const int cg = k0 + nj * 8 + (lane & 3) * 2;
                #pragma unroll
                for (int e = 0; e < 2; e++) {
                    float z0 = Sf[nj][e];
                    float z1 = Sf[nj][2 + e];
                    if (cg + e > r0g)     z0 = -INFINITY;
                    if (cg + e > r0g + 8) z1 = -INFINITY;
                    Sf[nj][e] = z0; Sf[nj][2 + e] = z1;
                    m0 = fmaxf(m0, z0); m1 = fmaxf(m1, z1);
                }
            }
        } else {
            // unmasked fast path: pure max scan
            #pragma unroll
            for (int nj = 0; nj < 8; nj++) {
                m0 = fmaxf(m0, fmaxf(Sf[nj][0], Sf[nj][1]));
                m1 = fmaxf(m1, fmaxf(Sf[nj][2], Sf[nj][3]));
            }
        }
        m0 = fmaxf(m0, __shfl_xor_sync(0xffffffffu, m0, 1));
        m0 = fmaxf(m0, __shfl_xor_sync(0xffffffffu, m0, 2));
        m1 = fmaxf(m1, __shfl_xor_sync(0xffffffffu, m1, 1));
        m1 = fmaxf(m1, __shfl_xor_sync(0xffffffffu, m1, 2));
        const float c0 = exp2f(zm0 - m0);
        const float c1 = exp2f(zm1 - m1);
        zm0 = m0; zm1 = m1;
        l0 *= c0; l1 *= c1;
        #pragma unroll
        for (int nj = 0; nj < 8; nj++) {
            O[nj][0] *= c0; O[nj][1] *= c0;
            O[nj][2] *= c1; O[nj][3] *= c1;
        }

        __half2 p01[8], p23[8];
        #pragma unroll
        for (int nj = 0; nj < 8; nj++) {
            p01[nj] = h2exp2(__floats2half2_rn(Sf[nj][0] - m0, Sf[nj][1] - m0));
            p23[nj] = h2exp2(__floats2half2_rn(Sf[nj][2] - m1, Sf[nj][3] - m1));
            const float2 f01 = __half22float2(p01[nj]);
            const float2 f23 = __half22float2(p23[nj]);
            l0 += f01.x + f01.y;
            l1 += f23.x + f23.y;
        }

        // ---- O += P V ----
        #pragma unroll
        for (int kc = 0; kc < 4; kc++) {
            uint32_t aP[4];
            aP[0] = *(uint32_t*)&p01[2 * kc];
            aP[1] = *(uint32_t*)&p23[2 * kc];
            aP[2] = *(uint32_t*)&p01[2 * kc + 1];
            aP[3] = *(uint32_t*)&p23[2 * kc + 1];
            #pragma unroll
            for (int j2 = 0; j2 < 4; j2++) {
                const int g = lane >> 3;
                const int r = kc * 16 + (g & 1) * 8 + (lane & 7);
                const int c = j2 * 16 + (g >> 1) * 8;
                const uint32_t off = (uint32_t)(r * 128 + c * 2);
                uint32_t b0, b1, b2, b3;
                LDSM4T(b0, b1, b2, b3, kvb + 8192 + (off ^ ((off >> 3) & 0x70)));
                uint32_t bA[2] = {b0, b1}, bB[2] = {b2, b3};
                MMA16816(O[2 * j2], aP, bA);
                MMA16816(O[2 * j2 + 1], aP, bB);
            }
        }

        stage = (stage == 2) ? 0 : stage + 1;
        nstage = (nstage == 2) ? 0 : nstage + 1;
    }

    l0 += __shfl_xor_sync(0xffffffffu, l0, 1);
    l0 += __shfl_xor_sync(0xffffffffu, l0, 2);
    l1 += __shfl_xor_sync(0xffffffffu, l1, 1);
    l1 += __shfl_xor_sync(0xffffffffu, l1, 2);
    const float i0 = 1.0f / l0, i1 = 1.0f / l1;

    __half* y0 = y + (size_t)(b * SEQ + r0g) * DMODEL + hh * HDIM;
    __half* y1 = y0 + (size_t)8 * DMODEL;
    #pragma unroll
    for (int nj = 0; nj < 8; nj++) {
        const int col = nj * 8 + (lane & 3) * 2;
        *(uint32_t*)(y0 + col) = pack_h2(O[nj][0] * i0, O[nj][1] * i0);
        *(uint32_t*)(y1 + col) = pack_h2(O[nj][2] * i1, O[nj][3] * i1);
    }
}

// =============================== launcher =====================================
extern "C" void kernel_launch(void* const* d_in, const int* in_sizes, int n_in,
                              void* d_out, int out_size) {
    const float* x      = (const float*)d_in[0];
    const float* ln1_w  = (const float*)d_in[1];
    const float* ln1_b  = (const float*)d_in[2];
    const float* ln2_w  = (const float*)d_in[3];
    const float* ln2_b  = (const float*)d_in[4];
    const float* w_attn = (const float*)d_in[5];
    const float* b_attn = (const float*)d_in[6];
    const float* w_proj = (const float*)d_in[7];
    const float* b_proj = (const float*)d_in[8];
    const float* w_fc   = (const float*)d_in[9];
    const float* b_fc   = (const float*)d_in[10];
    const float* w_fc2  = (const float*)d_in[11];
    const float* b_fc2  = (const float*)d_in[12];
    float* out = (float*)d_out;

    __half *h_h, *qkv_h, *y_h, *a_h, *wth_attn, *wth_proj, *wth_fc, *wth_fc2;
    float *x2;
    cudaGetSymbolAddress((void**)&h_h,      g_h_h);
    cudaGetSymbolAddress((void**)&qkv_h,    g_qkv_h);
    cudaGetSymbolAddress((void**)&y_h,      g_y_h);
    cudaGetSymbolAddress((void**)&x2,       g_x2);
    cudaGetSymbolAddress((void**)&a_h,      g_a_h);
    cudaGetSymbolAddress((void**)&wth_attn, g_wth_attn);
    cudaGetSymbolAddress((void**)&wth_proj, g_wth_proj);
    cudaGetSymbolAddress((void**)&wth_fc,   g_wth_fc);
    cudaGetSymbolAddress((void**)&wth_fc2,  g_wth_fc2);

    cudaFuncSetAttribute(attention_tc_kernel,
                         cudaFuncAttributeMaxDynamicSharedMemorySize, ATT_SMEM_BYTES);
    cudaFuncSetAttribute(hgemm_kernel<1>,
                         cudaFuncAttributeMaxDynamicSharedMemorySize, HGEMM_SMEM);
    cudaFuncSetAttribute(hgemm_kernel<2>,
                         cudaFuncAttributeMaxDynamicSharedMemorySize, HGEMM_SMEM);
    cudaFuncSetAttribute(hgemm_kernel<3>,
                         cudaFuncAttributeMaxDynamicSharedMemorySize, HGEMM_SMEM);

    // Side stream + events, lazily created on the FIRST (uncaptured) call.
    static cudaStream_t s2 = nullptr;
    static cudaEvent_t evFork = nullptr, evJoin = nullptr;
    if (s2 == nullptr) {
        cudaStreamCreateWithFlags(&s2, cudaStreamNonBlocking);
        cudaEventCreateWithFlags(&evFork, cudaEventDisableTiming);
        cudaEventCreateWithFlags(&evJoin, cudaEventDisableTiming);
    }

    // 0) fork: weight transpose on s2, LN1 on main stream
    cudaEventRecord(evFork, 0);
    cudaStreamWaitEvent(s2, evFork, 0);
    {
        dim3 tb(32, 8);
        transpose_all_kernel<<<12288, tb, 0, s2>>>(w_attn, w_proj, w_fc, w_fc2,
                                                   wth_attn, wth_proj, wth_fc, wth_fc2);
    }
    cudaEventRecord(evJoin, s2);

    // 1) h = LN1(x)  (fp16)
    layernorm_kernel<<<MROWS / 8, 256>>>(x, ln1_w, ln1_b, h_h);

    cudaStreamWaitEvent(0, evJoin, 0);

    // 2) qkv = h @ w_attn + b_attn       [4096,3072] K=1024  (fp16 out, Q scaled)
    hgemm_kernel<3><<<dim3(3 * DMODEL / 128, MROWS / 128), 256, HGEMM_SMEM>>>(
        h_h, wth_attn, b_attn, nullptr, qkv_h, 3 * DMODEL, DMODEL);

    // 3) y = attention(qkv)  (heavy-first, fp16 out)
    {
        dim3 grid(BATCH * NHEADS, SEQ / 128);
        attention_tc_kernel<<<grid, 256, ATT_SMEM_BYTES>>>(qkv_h, y_h);
    }

    // 4) x2 = x + y @ w_proj + b_proj    [4096,1024] K=1024  (fp32 out)
    hgemm_kernel<1><<<dim3(DMODEL / 128, MROWS / 128), 256, HGEMM_SMEM>>>(
        y_h, wth_proj, b_proj, x, x2, DMODEL, DMODEL);

    // 5) h = LN2(x2)  (fp16)
    layernorm_kernel<<<MROWS / 8, 256>>>(x2, ln2_w, ln2_b, h_h);

    // 6) a = gelu(h @ w_fc + b_fc)       [4096,4096] K=1024  (fp16 out)
    hgemm_kernel<2><<<dim3(4 * DMODEL / 128, MROWS / 128), 256, HGEMM_SMEM>>>(
        h_h, wth_fc, b_fc, nullptr, a_h, 4 * DMODEL, DMODEL);

    // 7) out = x2 + a @ w_fc2 + b_fc2    [4096,1024] K=4096  (fp32 out)
    hgemm_kernel<1><<<dim3(DMODEL / 128, MROWS / 128), 256, HGEMM_SMEM>>>(
        a_h, wth_fc2, b_fc2, x2, out, DMODEL, 4 * DMODEL);
}

// round 17
// speedup vs baseline: 1.0202x; 1.0043x over previous
#include <cuda_runtime.h>
#include <cuda_fp16.h>
#include <math.h>
#include <stdint.h>

#define BATCH 2
#define SEQ   2048
#define DMODEL 1024
#define NHEADS 16
#define HDIM  64
#define MROWS (BATCH*SEQ)          // 4096

#define L2E_SCALED 0.1803368801111204f   // 0.125 * log2(e), folded into Q at QKV epilogue

// ---------------- scratch (device globals) ------------------------------------
__device__ __half g_h_h [(size_t)MROWS * DMODEL];          // LN out (fp16)
__device__ __half g_qkv_h[(size_t)MROWS * 3 * DMODEL];     // QKV (fp16, Q pre-scaled)
__device__ __half g_y_h [(size_t)MROWS * DMODEL];          // attention out (fp16)
__device__ float  g_x2  [(size_t)MROWS * DMODEL];          // residual after attn (fp32)
__device__ __half g_a_h [(size_t)MROWS * 4 * DMODEL];      // MLP hidden (fp16)
__device__ __half g_wth_attn[(size_t)3 * DMODEL * DMODEL]; // [N,K] fp16
__device__ __half g_wth_proj[(size_t)DMODEL * DMODEL];
__device__ __half g_wth_fc  [(size_t)4 * DMODEL * DMODEL];
__device__ __half g_wth_fc2 [(size_t)4 * DMODEL * DMODEL];

// =========================== PTX helpers ======================================
__device__ __forceinline__ uint32_t pack_h2(float lo, float hi) {
    uint32_t u;
    asm("cvt.rn.f16x2.f32 %0, %1, %2;" : "=r"(u) : "f"(hi), "f"(lo));
    return u;
}
__device__ __forceinline__ void cp16(uint32_t dst, const void* src) {
    asm volatile("cp.async.cg.shared.global [%0], [%1], 16;" :: "r"(dst), "l"(src));
}
#define CP_COMMIT() asm volatile("cp.async.commit_group;" ::: "memory")
template <int N> __device__ __forceinline__ void cp_wait() {
    asm volatile("cp.async.wait_group %0;" :: "n"(N) : "memory");
}
#define LDSM4(r0, r1, r2, r3, addr) \
    asm volatile("ldmatrix.sync.aligned.m8n8.x4.shared.b16 {%0,%1,%2,%3}, [%4];" \
                 : "=r"(r0), "=r"(r1), "=r"(r2), "=r"(r3) : "r"(addr))
#define LDSM4T(r0, r1, r2, r3, addr) \
    asm volatile("ldmatrix.sync.aligned.m8n8.x4.trans.shared.b16 {%0,%1,%2,%3}, [%4];" \
                 : "=r"(r0), "=r"(r1), "=r"(r2), "=r"(r3) : "r"(addr))
#define MMA16816(d, a, b) \
    asm volatile("mma.sync.aligned.m16n8k16.row.col.f32.f16.f16.f32 " \
                 "{%0,%1,%2,%3}, {%4,%5,%6,%7}, {%8,%9}, {%0,%1,%2,%3};" \
                 : "+f"((d)[0]), "+f"((d)[1]), "+f"((d)[2]), "+f"((d)[3]) \
                 : "r"((a)[0]), "r"((a)[1]), "r"((a)[2]), "r"((a)[3]), \
                   "r"((b)[0]), "r"((b)[1]))

__device__ __forceinline__ float gelu_exact(float x) {
    return 0.5f * x * (1.0f + erff(x * 0.70710678118654752440f));
}

// ==================== LayerNorm: warp-per-row, 8 rows/block ====================
__global__ void __launch_bounds__(256)
layernorm_kernel(const float* __restrict__ src,
                 const float* __restrict__ w,
                 const float* __restrict__ b,
                 __half* __restrict__ dst) {
    const int lane = threadIdx.x & 31;
    const int row  = blockIdx.x * 8 + (threadIdx.x >> 5);
    const float4* srow = (const float4*)(src + (size_t)row * DMODEL);

    float4 v[8];
    float s = 0.f, q = 0.f;
    #pragma unroll
    for (int k = 0; k < 8; k++) {
        v[k] = srow[lane + 32 * k];
        s += v[k].x + v[k].y + v[k].z + v[k].w;
        q += v[k].x*v[k].x + v[k].y*v[k].y + v[k].z*v[k].z + v[k].w*v[k].w;
    }
    #pragma unroll
    for (int o = 16; o > 0; o >>= 1) {
        s += __shfl_xor_sync(0xffffffffu, s, o);
        q += __shfl_xor_sync(0xffffffffu, q, o);
    }
    const float mean = s * (1.0f / DMODEL);
    const float var  = q * (1.0f / DMODEL) - mean * mean;
    const float rstd = rsqrtf(var + 1e-5f);

    uint2* drow = (uint2*)(dst + (size_t)row * DMODEL);
    #pragma unroll
    for (int k = 0; k < 8; k++) {
        const float4 wv = ((const float4*)w)[lane + 32 * k];
        const float4 bv = ((const float4*)b)[lane + 32 * k];
        const float ox = (v[k].x - mean) * rstd * wv.x + bv.x;
        const float oy = (v[k].y - mean) * rstd * wv.y + bv.y;
        const float oz = (v[k].z - mean) * rstd * wv.z + bv.z;
        const float ow = (v[k].w - mean) * rstd * wv.w + bv.w;
        drow[lane + 32 * k] = make_uint2(pack_h2(ox, oy), pack_h2(oz, ow));
    }
}

// ===== weight transpose + fp16 [K,N]->[N,K]: attn-only and rest variants ======
__global__ void transpose_attn_kernel(const float* __restrict__ wa,
                                      __half* __restrict__ oa) {
    __shared__ float t[32][33];
    const int b = blockIdx.x;                    // 3072 blocks
    const int nb = (b % 96) * 32, kb = (b / 96) * 32;
    const int tx = threadIdx.x, ty = threadIdx.y;
    #pragma unroll
    for (int i = 0; i < 32; i += 8)
        t[ty + i][tx] = wa[(size_t)(kb + ty + i) * 3072 + nb + tx];
    __syncthreads();
    #pragma unroll
    for (int i = 0; i < 32; i += 8)
        oa[(size_t)(nb + ty + i) * 1024 + kb + tx] = __float2half_rn(t[tx][ty + i]);
}

__global__ void transpose_rest_kernel(const float* __restrict__ wp,
                                      const float* __restrict__ wf,
                                      const float* __restrict__ wf2,
                                      __half* __restrict__ op,
                                      __half* __restrict__ of,
                                      __half* __restrict__ of2) {
    __shared__ float t[32][33];
    const int bid = blockIdx.x;                  // 9216 blocks
    const float* src; __half* dst;
    int K, N, nb, kb;
    if (bid < 1024)      { const int b = bid;        src = wp;  dst = op;  K = 1024; N = 1024; nb = (b % 32) * 32;  kb = (b / 32) * 32; }
    else if (bid < 5120) { const int b = bid - 1024; src = wf;  dst = of;  K = 1024; N = 4096; nb = (b % 128) * 32; kb = (b / 128) * 32; }
    else                 { const int b = bid - 5120; src = wf2; dst = of2; K = 4096; N = 1024; nb = (b % 32) * 32;  kb = (b / 32) * 32; }
    const int tx = threadIdx.x, ty = threadIdx.y;
    #pragma unroll
    for (int i = 0; i < 32; i += 8)
        t[ty + i][tx] = src[(size_t)(kb + ty + i) * N + nb + tx];
    __syncthreads();
    #pragma unroll
    for (int i = 0; i < 32; i += 8)
        dst[(size_t)(nb + ty + i) * K + kb + tx] = __float2half_rn(t[tx][ty + i]);
}

// ======================= fp16 tensor-core GEMM (mma.sync) =====================
// C[M,N] = A[M,K](fp16) @ Bt[N,K](fp16)^T + bias (+ epilogue), fp32 accum.
// 128x128 CTA tile, 8 warps (2x4), warp tile 64x32, BK=64, 3-stage cp.async.
// EPI: 0 fp32+bias, 1 fp32+bias+res, 2 fp16 gelu, 3 fp16+bias with Q columns
// (c < DMODEL) pre-scaled by L2E_SCALED for the attention softmax.
template <int EPI>
__global__ void __launch_bounds__(256)
hgemm_kernel(const __half* __restrict__ A, const __half* __restrict__ Bt,
             const float* __restrict__ bias, const float* __restrict__ res,
             void* __restrict__ Cout, int N, int K) {
    extern __shared__ char smraw[];
    char* sm = smraw + ((1024 - ((uintptr_t)smraw & 1023)) & 1023);
    const uint32_t sbase = (uint32_t)__cvta_generic_to_shared(sm);

    const int tid  = threadIdx.x;
    const int lane = tid & 31, wid = tid >> 5;
    const int wm = wid >> 2, wn = wid & 3;
    const int bx = blockIdx.x, by = blockIdx.y;
    const int NK = K >> 6;

    const int lrow = tid >> 1;
    const int lch0 = (tid & 1) * 4;

    float acc[4][4][4];
    #pragma unroll
    for (int mi = 0; mi < 4; mi++)
        #pragma unroll
        for (int ni = 0; ni < 4; ni++)
            #pragma unroll
            for (int e = 0; e < 4; e++) acc[mi][ni][e] = 0.f;

    const __half* Ag = A + (size_t)(by * 128 + lrow) * K + lch0 * 8;
    const __half* Bg = Bt + (size_t)(bx * 128 + lrow) * K + lch0 * 8;
    uint32_t swoff[4];
    #pragma unroll
    for (int c = 0; c < 4; c++) {
        const uint32_t off = (uint32_t)(lrow * 128 + (lch0 + c) * 16);
        swoff[c] = off ^ ((off >> 3) & 0x70);
    }

    #pragma unroll
    for (int c2 = 0; c2 < 2; c2++) {
        const uint32_t base = sbase + c2 * 32768;
        const int kh = c2 << 6;
        #pragma unroll
        for (int c = 0; c < 4; c++) {
            cp16(base + swoff[c], Ag + kh + c * 8);
            cp16(base + 16384 + swoff[c], Bg + kh + c * 8);
        }
        CP_COMMIT();
    }

    int stage = 0, nstage = 2;
    for (int kt = 0; kt < NK; kt++) {
        if (kt + 2 < NK) cp_wait<1>(); else cp_wait<0>();
        __syncthreads();

        if (kt + 2 < NK) {
            const uint32_t base = sbase + nstage * 32768;
            const int kh = (kt + 2) << 6;
            #pragma unroll
            for (int c = 0; c < 4; c++) {
                cp16(base + swoff[c], Ag + kh + c * 8);
                cp16(base + 16384 + swoff[c], Bg + kh + c * 8);
            }
            CP_COMMIT();
        }

        const uint32_t abase = sbase + stage * 32768;
        const uint32_t bbase = abase + 16384;
        #pragma unroll
        for (int ks = 0; ks < 4; ks++) {
            uint32_t af[4][4];
            #pragma unroll
            for (int mi = 0; mi < 4; mi++) {
                const int r = wm * 64 + mi * 16 + (lane & 7) + 8 * ((lane >> 3) & 1);
                const int cb = (ks * 16 + 8 * ((lane >> 4) & 1)) * 2;
                const uint32_t off = (uint32_t)(r * 128 + cb);
                LDSM4(af[mi][0], af[mi][1], af[mi][2], af[mi][3],
                      abase + (off ^ ((off >> 3) & 0x70)));
            }
            uint32_t bf[4][2];
            #pragma unroll
            for (int np = 0; np < 2; np++) {
                const int r = wn * 32 + np * 16 + (lane & 7) + 8 * ((lane >> 4) & 1);
                const int cb = (ks * 16 + 8 * ((lane >> 3) & 1)) * 2;
                const uint32_t off = (uint32_t)(r * 128 + cb);
                uint32_t b0, b1, b2, b3;
                LDSM4(b0, b1, b2, b3, bbase + (off ^ ((off >> 3) & 0x70)));
                bf[np * 2][0] = b0; bf[np * 2][1] = b1;
                bf[np * 2 + 1][0] = b2; bf[np * 2 + 1][1] = b3;
            }
            #pragma unroll
            for (int mi = 0; mi < 4; mi++)
                #pragma unroll
                for (int ni = 0; ni < 4; ni++)
                    MMA16816(acc[mi][ni], af[mi], bf[ni]);
        }

        stage = (stage == 2) ? 0 : stage + 1;
        nstage = (nstage == 2) ? 0 : nstage + 1;
    }

    const int row0 = by * 128 + wm * 64;
    const int col0 = bx * 128 + wn * 32;
    #pragma unroll
    for (int mi = 0; mi < 4; mi++) {
        #pragma unroll
        for (int ni = 0; ni < 4; ni++) {
            const int r = row0 + mi * 16 + (lane >> 2);
            const int c = col0 + ni * 8 + (lane & 3) * 2;
            const float b0 = bias[c], b1 = bias[c + 1];
            float v0 = acc[mi][ni][0] + b0, v1 = acc[mi][ni][1] + b1;
            float v2 = acc[mi][ni][2] + b0, v3 = acc[mi][ni][3] + b1;
            if (EPI == 1) {
                const float2 r0 = *(const float2*)(res + (size_t)r * N + c);
                const float2 r1 = *(const float2*)(res + (size_t)(r + 8) * N + c);
                v0 += r0.x; v1 += r0.y; v2 += r1.x; v3 += r1.y;
            }
            if (EPI == 2) {
                __half* C = (__half*)Cout;
                *(uint32_t*)(C + (size_t)r * N + c) =
                    pack_h2(gelu_exact(v0), gelu_exact(v1));
                *(uint32_t*)(C + (size_t)(r + 8) * N + c) =
                    pack_h2(gelu_exact(v2), gelu_exact(v3));
            } else if (EPI == 3) {
                const float qs = (c < DMODEL) ? L2E_SCALED : 1.0f;
                __half* C = (__half*)Cout;
                *(uint32_t*)(C + (size_t)r * N + c) = pack_h2(v0 * qs, v1 * qs);
                *(uint32_t*)(C + (size_t)(r + 8) * N + c) = pack_h2(v2 * qs, v3 * qs);
            } else {
                float* C = (float*)Cout;
                *(float2*)(C + (size_t)r * N + c) = make_float2(v0, v1);
                *(float2*)(C + (size_t)(r + 8) * N + c) = make_float2(v2, v3);
            }
        }
    }
}

#define HGEMM_SMEM (3 * 32768 + 1024)

// ================== Tensor-core flash attention (fp16 MMA) ====================
// grid (32 bh, 16 qtIdx) with qt = 15 - by  => heavy tiles scheduled FIRST.
// Q pre-scaled by L2E_SCALED: S from MMA is already log2-domain.
// KV tiles of 128 keys, two 64-key halves per tile.
// RACE-FIX ordering each iter: cp_wait (own groups) -> __syncthreads (all
// threads' waits done => all cp.async data visible) -> prefetch -> consume.
// smem: Q 16KB @0 | 2 stages @16K + s*32K: K[128x128B] @+0, V @+16K. 80KB.
#define ATT_SMEM_BYTES (16384 + 2 * 32768)

__global__ void __launch_bounds__(256)
attention_tc_kernel(const __half* __restrict__ qkv, __half* __restrict__ y) {
    extern __shared__ char smatt[];
    const uint32_t sbase = (uint32_t)__cvta_generic_to_shared(smatt);

    const int tid = threadIdx.x, lane = tid & 31, w = tid >> 5;
    const int bh = blockIdx.x;
    const int qt = 15 - blockIdx.y;
    const int b = bh >> 4, hh = bh & 15;
    const int q0 = qt * 128;
    const int nkt = qt + 1;                    // tiles of 128 keys

    const __half* qbase = qkv + (size_t)(b * SEQ + q0) * (3 * DMODEL) + hh * HDIM;
    const __half* kbg = qkv + (size_t)b * SEQ * (3 * DMODEL) + DMODEL + hh * HDIM;
    const __half* vbg = kbg + DMODEL;

    // prologue: Q + stage0 (K/V rows 0..127) in one group
    for (int i = tid; i < 1024; i += 256) {
        const int r = i >> 3, ch = i & 7;
        const uint32_t off = (uint32_t)(r * 128 + ch * 16);
        const uint32_t sw = off ^ ((off >> 3) & 0x70);
        cp16(sbase + sw, qbase + (size_t)r * (3 * DMODEL) + ch * 8);
        cp16(sbase + 16384 + sw, kbg + (size_t)r * (3 * DMODEL) + ch * 8);
        cp16(sbase + 16384 + 16384 + sw, vbg + (size_t)r * (3 * DMODEL) + ch * 8);
    }
    CP_COMMIT();

    float O[8][4];
    #pragma unroll
    for (int nj = 0; nj < 8; nj++)
        #pragma unroll
        for (int e = 0; e < 4; e++) O[nj][e] = 0.f;
    float zm0 = -INFINITY, zm1 = -INFINITY, l0 = 0.f, l1 = 0.f;
    uint32_t aQ[4][4];

    const int r0g = q0 + w * 16 + (lane >> 2);

    for (int kt = 0; kt < nkt; kt++) {
        // drain the group that loaded stage kt&1 (my own), then barrier so that
        // EVERY thread's wait has completed => the whole stage is visible.
        cp_wait<0>();
        __syncthreads();

        // prefetch next stage (overwrites stage consumed at kt-1; the barrier
        // above guarantees all threads are past that consumption)
        if (kt + 1 < nkt) {
            const uint32_t nb = sbase + 16384 + ((kt + 1) & 1) * 32768;
            const int k0n = (kt + 1) * 128;
            for (int i = tid; i < 1024; i += 256) {
                const int r = i >> 3, ch = i & 7;
                const uint32_t off = (uint32_t)(r * 128 + ch * 16);
                const uint32_t sw = off ^ ((off >> 3) & 0x70);
                cp16(nb + sw, kbg + (size_t)(k0n + r) * (3 * DMODEL) + ch * 8);
                cp16(nb + 16384 + sw, vbg + (size_t)(k0n + r) * (3 * DMODEL) + ch * 8);
            }
            CP_COMMIT();
        }

        const uint32_t stg = sbase + 16384 + (kt & 1) * 32768;

        if (kt == 0) {
            #pragma unroll
            for (int kc = 0; kc < 4; kc++) {
                const int g = lane >> 3;
                const int r = w * 16 + (g & 1) * 8 + (lane & 7);
                const int c = kc * 16 + (g >> 1) * 8;
                const uint32_t off = (uint32_t)(r * 128 + c * 2);
                LDSM4(aQ[kc][0], aQ[kc][1], aQ[kc][2], aQ[kc][3],
                      sbase + (off ^ ((off >> 3) & 0x70)));
            }
        }

        // two 64-key halves from this 128-key stage
        #pragma unroll
        for (int h = 0; h < 2; h++) {
            const int k0 = kt * 128 + h * 64;
            const uint32_t kb_s = stg + h * 8192;           // K rows h*64..h*64+63
            const uint32_t vb_s = stg + 16384 + h * 8192;   // V rows

            // ---- S = Q K^T  (log2 domain) ----
            float Sf[8][4];
            #pragma unroll
            for (int nj = 0; nj < 8; nj++)
                #pragma unroll
                for (int e = 0; e < 4; e++) Sf[nj][e] = 0.f;
            #pragma unroll
            for (int kc = 0; kc < 4; kc++) {
                #pragma unroll
                for (int j2 = 0; j2 < 4; j2++) {
                    const int g = lane >> 3;
                    const int r = j2 * 16 + (g >> 1) * 8 + (lane & 7);
                    const int c = kc * 16 + (g & 1) * 8;
                    const uint32_t off = (uint32_t)(r * 128 + c * 2);
                    uint32_t b0, b1, b2, b3;
                    LDSM4(b0, b1, b2, b3, kb_s + (off ^ ((off >> 3) & 0x70)));
                    uint32_t bA[2] = {b0, b1}, bB[2] = {b2, b3};
                    MMA16816(Sf[2 * j2], aQ[kc], bA);
                    MMA16816(Sf[2 * j2 + 1], aQ[kc], bB);
                }
            }

            // ---- online softmax scan (mask-specialized) ----
            float m0 = zm0, m1 = zm1;
            if (k0 + 63 > q0) {
                #pragma unroll
                for (int nj = 0; nj < 8; nj++) {
                    const int cg = k0 + nj * 8 + (lane & 3) * 2;
                    #pragma unroll
                    for (int e = 0; e < 2; e++) {
                        float z0 = Sf[nj][e];
                        float z1 = Sf[nj][2 + e];
                        if (cg + e > r0g)     z0 = -INFINITY;
                        if (cg + e > r0g + 8) z1 = -INFINITY;
                        Sf[nj][e] = z0; Sf[nj][2 + e] = z1;
                        m0 = fmaxf(m0, z0); m1 = fmaxf(m1, z1);
                    }
                }
            } else {
                #pragma unroll
                for (int nj = 0; nj < 8; nj++) {
                    m0 = fmaxf(m0, fmaxf(Sf[nj][0], Sf[nj][1]));
                    m1 = fmaxf(m1, fmaxf(Sf[nj][2], Sf[nj][3]));
                }
            }
            m0 = fmaxf(m0, __shfl_xor_sync(0xffffffffu, m0, 1));
            m0 = fmaxf(m0, __shfl_xor_sync(0xffffffffu, m0, 2));
            m1 = fmaxf(m1, __shfl_xor_sync(0xffffffffu, m1, 1));
            m1 = fmaxf(m1, __shfl_xor_sync(0xffffffffu, m1, 2));
            const float c0 = exp2f(zm0 - m0);
            const float c1 = exp2f(zm1 - m1);
            zm0 = m0; zm1 = m1;
            l0 *= c0; l1 *= c1;
            #pragma unroll
            for (int nj = 0; nj < 8; nj++) {
                O[nj][0] *= c0; O[nj][1] *= c0;
                O[nj][2] *= c1; O[nj][3] *= c1;
            }

            __half2 p01[8], p23[8];
            #pragma unroll
            for (int nj = 0; nj < 8; nj++) {
                p01[nj] = h2exp2(__floats2half2_rn(Sf[nj][0] - m0, Sf[nj][1] - m0));
                p23[nj] = h2exp2(__floats2half2_rn(Sf[nj][2] - m1, Sf[nj][3] - m1));
                const float2 f01 = __half22float2(p01[nj]);
                const float2 f23 = __half22float2(p23[nj]);
                l0 += f01.x + f01.y;
                l1 += f23.x + f23.y;
            }

            // ---- O += P V ----
            #pragma unroll
            for (int kc = 0; kc < 4; kc++) {
                uint32_t aP[4];
                aP[0] = *(uint32_t*)&p01[2 * kc];
                aP[1] = *(uint32_t*)&p23[2 * kc];
                aP[2] = *(uint32_t*)&p01[2 * kc + 1];
                aP[3] = *(uint32_t*)&p23[2 * kc + 1];
                #pragma unroll
                for (int j2 = 0; j2 < 4; j2++) {
                    const int g = lane >> 3;
                    const int r = kc * 16 + (g & 1) * 8 + (lane & 7);
                    const int c = j2 * 16 + (g >> 1) * 8;
                    const uint32_t off = (uint32_t)(r * 128 + c * 2);
                    uint32_t b0, b1, b2, b3;
                    LDSM4T(b0, b1, b2, b3, vb_s + (off ^ ((off >> 3) & 0x70)));
                    uint32_t bA[2] = {b0, b1}, bB[2] = {b2, b3};
                    MMA16816(O[2 * j2], aP, bA);
                    MMA16816(O[2 * j2 + 1], aP, bB);
                }
            }
        }
    }

    l0 += __shfl_xor_sync(0xffffffffu, l0, 1);
    l0 += __shfl_xor_sync(0xffffffffu, l0, 2);
    l1 += __shfl_xor_sync(0xffffffffu, l1, 1);
    l1 += __shfl_xor_sync(0xffffffffu, l1, 2);
    const float i0 = 1.0f / l0, i1 = 1.0f / l1;

    __half* y0 = y + (size_t)(b * SEQ + r0g) * DMODEL + hh * HDIM;
    __half* y1 = y0 + (size_t)8 * DMODEL;
    #pragma unroll
    for (int nj = 0; nj < 8; nj++) {
        const int col = nj * 8 + (lane & 3) * 2;
        *(uint32_t*)(y0 + col) = pack_h2(O[nj][0] * i0, O[nj][1] * i0);
        *(uint32_t*)(y1 + col) = pack_h2(O[nj][2] * i1, O[nj][3] * i1);
    }
}

// =============================== launcher =====================================
extern "C" void kernel_launch(void* const* d_in, const int* in_sizes, int n_in,
                              void* d_out, int out_size) {
    const float* x      = (const float*)d_in[0];
    const float* ln1_w  = (const float*)d_in[1];
    const float* ln1_b  = (const float*)d_in[2];
    const float* ln2_w  = (const float*)d_in[3];
    const float* ln2_b  = (const float*)d_in[4];
    const float* w_attn = (const float*)d_in[5];
    const float* b_attn = (const float*)d_in[6];
    const float* w_proj = (const float*)d_in[7];
    const float* b_proj = (const float*)d_in[8];
    const float* w_fc   = (const float*)d_in[9];
    const float* b_fc   = (const float*)d_in[10];
    const float* w_fc2  = (const float*)d_in[11];
    const float* b_fc2  = (const float*)d_in[12];
    float* out = (float*)d_out;

    __half *h_h, *qkv_h, *y_h, *a_h, *wth_attn, *wth_proj, *wth_fc, *wth_fc2;
    float *x2;
    cudaGetSymbolAddress((void**)&h_h,      g_h_h);
    cudaGetSymbolAddress((void**)&qkv_h,    g_qkv_h);
    cudaGetSymbolAddress((void**)&y_h,      g_y_h);
    cudaGetSymbolAddress((void**)&x2,       g_x2);
    cudaGetSymbolAddress((void**)&a_h,      g_a_h);
    cudaGetSymbolAddress((void**)&wth_attn, g_wth_attn);
    cudaGetSymbolAddress((void**)&wth_proj, g_wth_proj);
    cudaGetSymbolAddress((void**)&wth_fc,   g_wth_fc);
    cudaGetSymbolAddress((void**)&wth_fc2,  g_wth_fc2);

    cudaFuncSetAttribute(attention_tc_kernel,
                         cudaFuncAttributeMaxDynamicSharedMemorySize, ATT_SMEM_BYTES);
    cudaFuncSetAttribute(hgemm_kernel<1>,
                         cudaFuncAttributeMaxDynamicSharedMemorySize, HGEMM_SMEM);
    cudaFuncSetAttribute(hgemm_kernel<2>,
                         cudaFuncAttributeMaxDynamicSharedMemorySize, HGEMM_SMEM);
    cudaFuncSetAttribute(hgemm_kernel<3>,
                         cudaFuncAttributeMaxDynamicSharedMemorySize, HGEMM_SMEM);

    // Side stream + events, lazily created on the FIRST (uncaptured) call.
    static cudaStream_t s2 = nullptr;
    static cudaEvent_t evFork = nullptr, evJoin1 = nullptr, evJoin2 = nullptr;
    if (s2 == nullptr) {
        cudaStreamCreateWithFlags(&s2, cudaStreamNonBlocking);
        cudaEventCreateWithFlags(&evFork, cudaEventDisableTiming);
        cudaEventCreateWithFlags(&evJoin1, cudaEventDisableTiming);
        cudaEventCreateWithFlags(&evJoin2, cudaEventDisableTiming);
    }

    // 0) fork: transposes on s2 (attn first, rest after); LN1 on main stream
    cudaEventRecord(evFork, 0);
    cudaStreamWaitEvent(s2, evFork, 0);
    {
        dim3 tb(32, 8);
        transpose_attn_kernel<<<3072, tb, 0, s2>>>(w_attn, wth_attn);
        cudaEventRecord(evJoin1, s2);
        transpose_rest_kernel<<<9216, tb, 0, s2>>>(w_proj, w_fc, w_fc2,
                                                   wth_proj, wth_fc, wth_fc2);
        cudaEventRecord(evJoin2, s2);
    }

    // 1) h = LN1(x)  (fp16)
    layernorm_kernel<<<MROWS / 8, 256>>>(x, ln1_w, ln1_b, h_h);

    // join 1: QKV needs only wth_attn
    cudaStreamWaitEvent(0, evJoin1, 0);

    // 2) qkv = h @ w_attn + b_attn       [4096,3072] K=1024  (fp16 out, Q scaled)
    hgemm_kernel<3><<<dim3(3 * DMODEL / 128, MROWS / 128), 256, HGEMM_SMEM>>>(
        h_h, wth_attn, b_attn, nullptr, qkv_h, 3 * DMODEL, DMODEL);

    // 3) y = attention(qkv)  (heavy-first, fp16 out)
    {
        dim3 grid(BATCH * NHEADS, SEQ / 128);
        attention_tc_kernel<<<grid, 256, ATT_SMEM_BYTES>>>(qkv_h, y_h);
    }

    // join 2: remaining GEMMs need proj/fc/fc2 weights
    cudaStreamWaitEvent(0, evJoin2, 0);

    // 4) x2 = x + y @ w_proj + b_proj    [4096,1024] K=1024  (fp32 out)
    hgemm_kernel<1><<<dim3(DMODEL / 128, MROWS / 128), 256, HGEMM_SMEM>>>(
        y_h, wth_proj, b_proj, x, x2, DMODEL, DMODEL);

    // 5) h = LN2(x2)  (fp16)
    layernorm_kernel<<<MROWS / 8, 256>>>(x2, ln2_w, ln2_b, h_h);

    // 6) a = gelu(h @ w_fc + b_fc)       [4096,4096] K=1024  (fp16 out)
    hgemm_kernel<2><<<dim3(4 * DMODEL / 128, MROWS / 128), 256, HGEMM_SMEM>>>(
        h_h, wth_fc, b_fc, nullptr, a_h, 4 * DMODEL, DMODEL);

    // 7) out = x2 + a @ w_fc2 + b_fc2    [4096,1024] K=4096  (fp32 out)
    hgemm_kernel<1><<<dim3(DMODEL / 128, MROWS / 128), 256, HGEMM_SMEM>>>(
        a_h, wth_fc2, b_fc2, x2, out, DMODEL, 4 * DMODEL);
}